// round 6
// baseline (speedup 1.0000x reference)
#include <cuda_runtime.h>
#include <math.h>
#include <stdint.h>

// ---------------- problem constants (fixed shapes) ----------------
#define H      128
#define FILT   128
#define NGAUSS 50
#define NMAX   50000
#define EMAX   800000
#define SPACING  (10.0f/49.0f)
#define GCOEFF   (-12.005f)            // -0.5/(10/49)^2
#define PI_OVER_CUT 0.3141592653589793f

#define EW   16      // warps per edge-kernel block
#define EPB  8       // edges per warp-group
#define GROW 10      // padded row stride (floats) for g/a arrays
#define PWF  (NGAUSS*GROW + FILT*GROW)   // per-warp smem floats = 500+1280 = 1780

#define INSTR 36     // k-major ins_t row stride (floats): 16B-aligned rows

// ---------------- scratch (device globals; no allocation allowed) ----------------
// __align__(128): vector (16B) accesses + red.global.add.v4 require 16B
// alignment; plain float arrays only guarantee 4B.
__device__ __align__(128) float g_h  [NMAX * H];
__device__ __align__(128) float g_xl [NMAX * H];
__device__ __align__(128) float g_agg[NMAX * H];
__device__ __align__(128) float g_tmp[NMAX * H];
__device__ __align__(128) float g_d  [EMAX];
__device__ __align__(128) float g_cut[EMAX];

// shifted softplus: log(1+e^x) - log2 = log(0.5 + 0.5*e^x)
__device__ __forceinline__ float ssp(float x) {
    return __logf(0.5f + 0.5f * __expf(x));
}

#define FFMA2(acc, a, b) \
    asm("fma.rn.f32x2 %0, %1, %2, %0;" : "+l"(acc) : "l"(a), "l"(b))

__device__ __forceinline__ unsigned long long dupf(float v) {
    unsigned long long r; unsigned x = __float_as_uint(v);
    asm("mov.b64 %0, {%1,%1};" : "=l"(r) : "r"(x));
    return r;
}
__device__ __forceinline__ float2 unpack2(unsigned long long v) {
    float a, b;
    asm("mov.b64 {%0,%1}, %2;" : "=f"(a), "=f"(b) : "l"(v));
    return make_float2(a, b);
}

// ---------------- edge geometry precompute ----------------
__global__ void prep_kernel(const float* __restrict__ pos,
                            const int* __restrict__ ei, int E) {
    int e = blockIdx.x * blockDim.x + threadIdx.x;
    if (e >= E) return;
    int s = ei[e];
    int t = ei[E + e];
    float dx = pos[3*s+0] - pos[3*t+0];
    float dy = pos[3*s+1] - pos[3*t+1];
    float dz = pos[3*s+2] - pos[3*t+2];
    float d = sqrtf(dx*dx + dy*dy + dz*dz);
    g_d[e]   = d;
    g_cut[e] = 0.5f * (cosf(d * PI_OVER_CUT) + 1.0f);
}

// ---------------- embedding ----------------
__global__ void embed_kernel(const int* __restrict__ atoms,
                             const float* __restrict__ emb, int N) {
    int i = blockIdx.x * blockDim.x + threadIdx.x;
    if (i >= N * H) return;
    g_h[i] = emb[atoms[i >> 7] * H + (i & (H - 1))];
}

// ---------------- fused GEMM: out = [ssp](in @ W + bias) [+ resid] ----------------
// in: [nrows,128] row-major, W: [128,KC], out: [nrows,KC]. blockDim = KC, 32 rows/block.
// Inner loop uses row-pair-packed fma.rn.f32x2; ins staged k-major (stride INSTR)
// so ld.shared.v2.u64 yields ready-packed row pairs (uniform broadcast reads).
// If zero_agg != 0, also zeroes this block's 32 rows of g_agg (saves a memset pass).
template <int KC>
__global__ void gemm_kernel(const float* __restrict__ in,
                            const float* __restrict__ W,
                            const float* __restrict__ bias,
                            const float* __restrict__ resid,
                            float* __restrict__ out,
                            int nrows, int act, int zero_agg) {
    extern __shared__ float sm[];
    float* ws  = sm;                 // 128*KC
    float* bs  = ws + 128 * KC;      // KC
    float* ins = bs + KC;            // 128*INSTR (k-major, padded)
    int c = threadIdx.x;

    for (int idx = c; idx < 128 * KC; idx += KC) ws[idx] = W[idx];
    bs[c] = bias ? bias[c] : 0.0f;

    int r0 = blockIdx.x * 32;
    for (int idx = c; idx < 32 * 128; idx += KC) {
        int r = idx >> 7, k = idx & 127;
        ins[k * INSTR + r] = (r0 + r < nrows) ? in[(size_t)(r0 + r) * 128 + k] : 0.0f;
    }

    if (zero_agg) {
        // zero g_agg rows [r0, r0+32) (KC==128 path only in practice)
        for (int idx = c; idx < 32 * 128; idx += KC) {
            int r = r0 + (idx >> 7);
            if (r < nrows) g_agg[(size_t)r * 128 + (idx & 127)] = 0.0f;
        }
    }
    __syncthreads();

    unsigned long long bd = dupf(bs[c]);
    unsigned long long acc[16];
#pragma unroll
    for (int p = 0; p < 16; p++) acc[p] = bd;

#pragma unroll 4
    for (int k = 0; k < 128; k++) {
        unsigned long long wd = dupf(ws[k * KC + c]);
        const ulonglong2* rowp = (const ulonglong2*)(ins + k * INSTR);
#pragma unroll
        for (int q = 0; q < 8; q++) {
            ulonglong2 pr = rowp[q];           // rows {4q,4q+1},{4q+2,4q+3}
            FFMA2(acc[2 * q],     pr.x, wd);
            FFMA2(acc[2 * q + 1], pr.y, wd);
        }
    }

#pragma unroll
    for (int p = 0; p < 16; p++) {
        float2 t = unpack2(acc[p]);
#pragma unroll
        for (int h = 0; h < 2; h++) {
            int row = r0 + 2 * p + h;
            if (row < nrows) {
                float v = h ? t.y : t.x;
                if (act) v = ssp(v);
                if (resid) v += resid[(size_t)row * KC + c];
                out[(size_t)row * KC + c] = v;
            }
        }
    }
}

// ---------------- fused edge pipeline: 8 edges per warp, f32x2 edge-pair packing ----------------
// Lane owns channels 4L..4L+3. Accumulators: acc[ch i][edge-pair p] as packed f32x2.
// g/a arrays per-warp in smem, row stride GROW floats -> b64 pair loads, no packing movs.
__global__ __launch_bounds__(32 * EW, 1)
void edge_kernel(const int* __restrict__ ei,
                 const float* __restrict__ w1,
                 const float* __restrict__ b1,
                 const float* __restrict__ w2,
                 const float* __restrict__ b2, int E) {
    extern __shared__ float sm[];
    float* w1s = sm;                          // 50*128 = 6400
    float* w2s = w1s + NGAUSS * FILT;         // 128*128 = 16384
    float* b1s = w2s + FILT * FILT;           // 128
    float* b2s = b1s + FILT;                  // 128
    float* pw  = b2s + FILT;                  // EW * PWF

    int tid = threadIdx.x;
    for (int i = tid; i < NGAUSS * FILT; i += 32 * EW) w1s[i] = w1[i];
    for (int i = tid; i < FILT * FILT;  i += 32 * EW) w2s[i] = w2[i];
    if (tid < FILT) { b1s[tid] = b1[tid]; b2s[tid] = b2[tid]; }
    __syncthreads();

    const int wid = tid >> 5;
    const int L   = tid & 31;
    float* gw = pw + wid * PWF;               // [50][GROW]
    float* aw = gw + NGAUSS * GROW;           // [128][GROW]

    // duplicated biases for lane's 4 channels
    unsigned long long b1d[4], b2d[4];
#pragma unroll
    for (int i = 0; i < 4; i++) {
        b1d[i] = dupf(b1s[4 * L + i]);
        b2d[i] = dupf(b2s[4 * L + i]);
    }

    const long long stride = (long long)gridDim.x * EW * EPB;
    for (long long base = ((long long)blockIdx.x * EW + wid) * EPB; base < E;
         base += stride) {

        // lanes 0..7 load per-edge data (clamped; C=0 kills padded edges)
        long long jl = base + L; if (jl > (long long)E - 1) jl = E - 1;
        int j = (int)jl;
        int sj = 0, tj = 0; float dj = 0.f, Cj = 0.f;
        if (L < EPB) {
            sj = ei[j]; tj = ei[E + j]; dj = g_d[j];
            Cj = (base + L < E) ? g_cut[j] : 0.f;
        }
        float de[EPB];
#pragma unroll
        for (int e = 0; e < EPB; e++) de[e] = __shfl_sync(0xffffffffu, dj, e);

        // gaussians: lane computes rows k=L and k=L+32 (pairs over edges)
        {
            float off = (float)L * SPACING;
#pragma unroll
            for (int p = 0; p < 4; p++) {
                float ua = de[2*p]   - off;
                float ub = de[2*p+1] - off;
                *(float2*)(gw + GROW * L + 2 * p) =
                    make_float2(__expf(GCOEFF * ua * ua), __expf(GCOEFF * ub * ub));
            }
            if (L < NGAUSS - 32) {
                int k2 = L + 32;
                float o2 = (float)k2 * SPACING;
#pragma unroll
                for (int p = 0; p < 4; p++) {
                    float ua = de[2*p]   - o2;
                    float ub = de[2*p+1] - o2;
                    *(float2*)(gw + GROW * k2 + 2 * p) =
                        make_float2(__expf(GCOEFF * ua * ua), __expf(GCOEFF * ub * ub));
                }
            }
        }
        __syncwarp();

        // ---- stage 1: [8,50] @ [50,128] + b1 ----
        unsigned long long u[4][4];
#pragma unroll
        for (int i = 0; i < 4; i++) {
            u[i][0] = b1d[i]; u[i][1] = b1d[i]; u[i][2] = b1d[i]; u[i][3] = b1d[i];
        }
#pragma unroll 2
        for (int k = 0; k < NGAUSS; k++) {
            const float4 wv = *(const float4*)(w1s + k * FILT + 4 * L);
            unsigned long long wd0 = dupf(wv.x), wd1 = dupf(wv.y),
                               wd2 = dupf(wv.z), wd3 = dupf(wv.w);
#pragma unroll
            for (int p = 0; p < 4; p++) {
                unsigned long long a2 =
                    *(const unsigned long long*)(gw + GROW * k + 2 * p);
                FFMA2(u[0][p], a2, wd0);
                FFMA2(u[1][p], a2, wd1);
                FFMA2(u[2][p], a2, wd2);
                FFMA2(u[3][p], a2, wd3);
            }
        }

        // ssp + transpose into aw[k][e]
#pragma unroll
        for (int i = 0; i < 4; i++) {
#pragma unroll
            for (int p = 0; p < 4; p++) {
                float2 t = unpack2(u[i][p]);
                *(float2*)(aw + GROW * (4 * L + i) + 2 * p) =
                    make_float2(ssp(t.x), ssp(t.y));
            }
        }
        __syncwarp();

        // ---- stage 2: [8,128] @ [128,128] + b2 ----
        unsigned long long y[4][4];
#pragma unroll
        for (int i = 0; i < 4; i++) {
            y[i][0] = b2d[i]; y[i][1] = b2d[i]; y[i][2] = b2d[i]; y[i][3] = b2d[i];
        }
#pragma unroll 2
        for (int k = 0; k < FILT; k++) {
            const float4 wv = *(const float4*)(w2s + k * FILT + 4 * L);
            unsigned long long wd0 = dupf(wv.x), wd1 = dupf(wv.y),
                               wd2 = dupf(wv.z), wd3 = dupf(wv.w);
#pragma unroll
            for (int p = 0; p < 4; p++) {
                unsigned long long a2 =
                    *(const unsigned long long*)(aw + GROW * k + 2 * p);
                FFMA2(y[0][p], a2, wd0);
                FFMA2(y[1][p], a2, wd1);
                FFMA2(y[2][p], a2, wd2);
                FFMA2(y[3][p], a2, wd3);
            }
        }

        // ---- message: m = xl[src] * (y * C), scatter-add to agg[dst] ----
#pragma unroll
        for (int e = 0; e < EPB; e++) {
            int   sE = __shfl_sync(0xffffffffu, sj, e);
            int   tE = __shfl_sync(0xffffffffu, tj, e);
            float CE = __shfl_sync(0xffffffffu, Cj, e);
            const float4 xv = *(const float4*)(g_xl + (size_t)sE * H + 4 * L);
            const int p = e >> 1;
            float y0, y1, y2, y3;
            if ((e & 1) == 0) {
                y0 = unpack2(y[0][p]).x; y1 = unpack2(y[1][p]).x;
                y2 = unpack2(y[2][p]).x; y3 = unpack2(y[3][p]).x;
            } else {
                y0 = unpack2(y[0][p]).y; y1 = unpack2(y[1][p]).y;
                y2 = unpack2(y[2][p]).y; y3 = unpack2(y[3][p]).y;
            }
            float m0 = y0 * CE * xv.x;
            float m1 = y1 * CE * xv.y;
            float m2 = y2 * CE * xv.z;
            float m3 = y3 * CE * xv.w;
            float* dp = g_agg + (size_t)tE * H + 4 * L;
            asm volatile("red.global.add.v4.f32 [%0], {%1, %2, %3, %4};"
                         :: "l"(dp), "f"(m0), "f"(m1), "f"(m2), "f"(m3)
                         : "memory");
        }
        __syncwarp();   // protect gw/aw reuse across iterations
    }
}

// ---------------- readout: e/q dots + segment sums ----------------
__global__ void readout2_kernel(const float* __restrict__ hh,  // [N,64]
                                const float* __restrict__ ew, const float* __restrict__ ebp,
                                const float* __restrict__ qw, const float* __restrict__ qbp,
                                const int* __restrict__ batch,
                                float* __restrict__ out, int N, int G) {
    int gw_id = (blockIdx.x * blockDim.x + threadIdx.x) >> 5;
    int lane  = threadIdx.x & 31;
    if (gw_id >= N) return;
    float h0 = hh[(size_t)gw_id * 64 + lane];
    float h1 = hh[(size_t)gw_id * 64 + 32 + lane];
    float e = h0 * ew[lane] + h1 * ew[lane + 32];
    float q = h0 * qw[lane] + h1 * qw[lane + 32];
#pragma unroll
    for (int o = 16; o > 0; o >>= 1) {
        e += __shfl_down_sync(0xffffffffu, e, o);
        q += __shfl_down_sync(0xffffffffu, q, o);
    }
    if (lane == 0) {
        e += ebp[0];
        q += qbp[0];
        out[gw_id]     = e;
        out[N + gw_id] = q;
        int b = batch[gw_id];
        atomicAdd(out + 2 * N + b,     e);
        atomicAdd(out + 2 * N + G + b, q);
    }
}

// ---------------- host launcher ----------------
extern "C" void kernel_launch(void* const* d_in, const int* in_sizes, int n_in,
                              void* d_out, int out_size) {
    const int*   atoms   = (const int*)  d_in[0];
    const float* pos     = (const float*)d_in[1];
    const int*   batch   = (const int*)  d_in[2];
    const int*   ei      = (const int*)  d_in[3];
    const float* emb     = (const float*)d_in[4];
    const float* mlp_w1  = (const float*)d_in[5];
    const float* mlp_b1  = (const float*)d_in[6];
    const float* mlp_w2  = (const float*)d_in[7];
    const float* mlp_b2  = (const float*)d_in[8];
    const float* conv_w1 = (const float*)d_in[9];
    const float* conv_w2 = (const float*)d_in[10];
    const float* conv_b2 = (const float*)d_in[11];
    const float* int_w   = (const float*)d_in[12];
    const float* int_b   = (const float*)d_in[13];
    const float* lin1_w  = (const float*)d_in[14];
    const float* lin1_b  = (const float*)d_in[15];
    const float* e_w     = (const float*)d_in[16];
    const float* e_b     = (const float*)d_in[17];
    const float* q_w     = (const float*)d_in[18];
    const float* q_b     = (const float*)d_in[19];
    float* out = (float*)d_out;

    const int N = in_sizes[0];
    const int E = in_sizes[3] / 2;
    const int G = (out_size - 2 * N) / 2;
    const int L = in_sizes[5] / (NGAUSS * FILT);

    void *hp_, *xlp_, *aggp_, *tmpp_;
    cudaGetSymbolAddress(&hp_,   g_h);
    cudaGetSymbolAddress(&xlp_,  g_xl);
    cudaGetSymbolAddress(&aggp_, g_agg);
    cudaGetSymbolAddress(&tmpp_, g_tmp);
    float* hp   = (float*)hp_;
    float* xlp  = (float*)xlp_;
    float* aggp = (float*)aggp_;
    float* tmpp = (float*)tmpp_;

    const size_t gemm128_smem = (size_t)(128 * 128 + 128 + 128 * INSTR) * sizeof(float);
    const size_t gemm64_smem  = (size_t)(128 * 64  + 64  + 128 * INSTR) * sizeof(float);
    const size_t edge_smem    = (size_t)(NGAUSS * FILT + FILT * FILT + 2 * FILT
                                         + EW * PWF) * sizeof(float);

    cudaFuncSetAttribute(gemm_kernel<128>, cudaFuncAttributeMaxDynamicSharedMemorySize, (int)gemm128_smem);
    cudaFuncSetAttribute(gemm_kernel<64>,  cudaFuncAttributeMaxDynamicSharedMemorySize, (int)gemm64_smem);
    cudaFuncSetAttribute(edge_kernel,      cudaFuncAttributeMaxDynamicSharedMemorySize, (int)edge_smem);

    prep_kernel<<<(E + 255) / 256, 256>>>(pos, ei, E);
    embed_kernel<<<(N * H + 255) / 256, 256>>>(atoms, emb, N);

    const int gemm_blocks = (N + 31) / 32;
    for (int l = 0; l < L; l++) {
        // xl = h @ conv_w1[l]  (also zeroes g_agg rows for this layer)
        gemm_kernel<128><<<gemm_blocks, 128, gemm128_smem>>>(
            hp, conv_w1 + (size_t)l * H * FILT, nullptr, nullptr, xlp, N, 0, 1);
        // fused edge MLP + gather/scatter (persistent, 1 block/SM)
        edge_kernel<<<148, 32 * EW, edge_smem>>>(
            ei,
            mlp_w1 + (size_t)l * NGAUSS * FILT,
            mlp_b1 + (size_t)l * FILT,
            mlp_w2 + (size_t)l * FILT * FILT,
            mlp_b2 + (size_t)l * FILT, E);
        // tmp = ssp(agg @ conv_w2[l] + b2)
        gemm_kernel<128><<<gemm_blocks, 128, gemm128_smem>>>(
            aggp, conv_w2 + (size_t)l * FILT * H, conv_b2 + (size_t)l * H,
            nullptr, tmpp, N, 1, 0);
        // h = h + tmp @ int_w[l] + int_b[l]
        gemm_kernel<128><<<gemm_blocks, 128, gemm128_smem>>>(
            tmpp, int_w + (size_t)l * H * H, int_b + (size_t)l * H,
            hp, hp, N, 0, 0);
    }

    // hh = ssp(h @ lin1_w + lin1_b)  -> reuse g_tmp as [N,64]
    gemm_kernel<64><<<gemm_blocks, 64, gemm64_smem>>>(
        hp, lin1_w, lin1_b, nullptr, tmpp, N, 1, 0);

    cudaMemsetAsync(out + 2 * N, 0, (size_t)2 * G * sizeof(float));
    readout2_kernel<<<(N * 32 + 255) / 256, 256>>>(
        tmpp, e_w, e_b, q_w, q_b, batch, out, N, G);
}

// round 14
// speedup vs baseline: 1.1661x; 1.1661x over previous
#include <cuda_runtime.h>
#include <math.h>
#include <stdint.h>

// ---------------- problem constants (fixed shapes) ----------------
#define H      128
#define FILT   128
#define NGAUSS 50
#define NMAX   50000
#define EMAX   800000
#define SPACING  (10.0f/49.0f)
#define GCOEFF   (-12.005f)            // -0.5/(10/49)^2
#define PI_OVER_CUT 0.3141592653589793f

#define EW   18      // warps per edge-kernel block (smem: 92160 + 18*7120 = 220320B < opt-in max)
#define EPB  8       // edges per warp-group
#define GROW 10      // padded row stride (floats) for g/a arrays
#define PWF  (NGAUSS*GROW + FILT*GROW)   // per-warp smem floats = 500+1280 = 1780

#define GW   16      // warps per node-GEMM block
#define NROW 8       // rows per warp in node GEMM

// ---------------- scratch (device globals; no allocation allowed) ----------------
__device__ __align__(128) float g_h  [NMAX * H];
__device__ __align__(128) float g_xl [NMAX * H];
__device__ __align__(128) float g_agg[NMAX * H];
__device__ __align__(128) float g_tmp[NMAX * H];
__device__ __align__(128) float g_d  [EMAX];
__device__ __align__(128) float g_cut[EMAX];

// shifted softplus: log(1+e^x) - log2 = log(0.5 + 0.5*e^x)
__device__ __forceinline__ float ssp(float x) {
    return __logf(0.5f + 0.5f * __expf(x));
}

#define FFMA2(acc, a, b) \
    asm("fma.rn.f32x2 %0, %1, %2, %0;" : "+l"(acc) : "l"(a), "l"(b))

__device__ __forceinline__ unsigned long long dupf(float v) {
    unsigned long long r; unsigned x = __float_as_uint(v);
    asm("mov.b64 %0, {%1,%1};" : "=l"(r) : "r"(x));
    return r;
}
__device__ __forceinline__ float2 unpack2(unsigned long long v) {
    float a, b;
    asm("mov.b64 {%0,%1}, %2;" : "=f"(a), "=f"(b) : "l"(v));
    return make_float2(a, b);
}

// ---------------- edge geometry precompute ----------------
__global__ void prep_kernel(const float* __restrict__ pos,
                            const int* __restrict__ ei, int E) {
    int e = blockIdx.x * blockDim.x + threadIdx.x;
    if (e >= E) return;
    int s = ei[e];
    int t = ei[E + e];
    float dx = pos[3*s+0] - pos[3*t+0];
    float dy = pos[3*s+1] - pos[3*t+1];
    float dz = pos[3*s+2] - pos[3*t+2];
    float d = sqrtf(dx*dx + dy*dy + dz*dz);
    g_d[e]   = d;
    g_cut[e] = 0.5f * (cosf(d * PI_OVER_CUT) + 1.0f);
}

// ---------------- embedding ----------------
__global__ void embed_kernel(const int* __restrict__ atoms,
                             const float* __restrict__ emb, int N) {
    int i = blockIdx.x * blockDim.x + threadIdx.x;
    if (i >= N * H) return;
    g_h[i] = emb[atoms[i >> 7] * H + (i & (H - 1))];
}

// ---------------- node GEMM (KC=128): out = [ssp](in @ W + bias) [+ resid] ----------------
// Warp owns 8 rows, lane owns 4 cols. Per k:
// 1 LDS.128 (weights) + 4 dup movs + 4 broadcast LDS.64 (row pairs) + 16 FFMA2.
// Persistent grid: weights loaded into smem ONCE per SM.
// If zero_agg != 0, also zeroes the processed rows of g_agg.
__global__ __launch_bounds__(32 * GW, 1)
void ngemm_kernel(const float* __restrict__ in,
                  const float* __restrict__ W,
                  const float* __restrict__ bias,
                  const float* __restrict__ resid,
                  float* __restrict__ out,
                  int nrows, int act, int zero_agg) {
    extern __shared__ float sm[];
    float* ws = sm;                       // 128*128
    float* bs = ws + 128 * 128;           // 128
    float* pw = bs + 128;                 // GW * 128 * GROW (per-warp k-major staging)

    int tid = threadIdx.x;
    for (int i = tid; i < 128 * 128; i += 32 * GW) ws[i] = W[i];
    if (tid < 128) bs[tid] = bias ? bias[tid] : 0.0f;
    __syncthreads();

    const int wid = tid >> 5;
    const int L   = tid & 31;
    float* st = pw + wid * (128 * GROW);  // [128 k][GROW] (8 rows + 2 pad)

    unsigned long long bd[4];
#pragma unroll
    for (int i = 0; i < 4; i++) bd[i] = dupf(bs[4 * L + i]);

    const int ngroups = (nrows + NROW - 1) / NROW;
    const int gstride = gridDim.x * GW;
    for (int g = blockIdx.x * GW + wid; g < ngroups; g += gstride) {
        const int r0 = g * NROW;

        // stage 8 rows k-major: st[k][r] = in[r0+r][k]; coalesced LDG
        for (int i = L; i < NROW * 128; i += 32) {
            int r = i >> 7, k = i & 127;
            float v = (r0 + r < nrows) ? in[(size_t)(r0 + r) * 128 + k] : 0.0f;
            st[k * GROW + r] = v;
            if (zero_agg && r0 + r < nrows) g_agg[(size_t)(r0 + r) * 128 + k] = 0.0f;
        }
        __syncwarp();

        unsigned long long acc[4][4];
#pragma unroll
        for (int i = 0; i < 4; i++) {
            acc[i][0] = bd[i]; acc[i][1] = bd[i]; acc[i][2] = bd[i]; acc[i][3] = bd[i];
        }

#pragma unroll 2
        for (int k = 0; k < 128; k++) {
            const float4 wv = *(const float4*)(ws + k * 128 + 4 * L);
            unsigned long long wd0 = dupf(wv.x), wd1 = dupf(wv.y),
                               wd2 = dupf(wv.z), wd3 = dupf(wv.w);
#pragma unroll
            for (int p = 0; p < 4; p++) {
                unsigned long long a2 =
                    *(const unsigned long long*)(st + k * GROW + 2 * p);
                FFMA2(acc[0][p], a2, wd0);
                FFMA2(acc[1][p], a2, wd1);
                FFMA2(acc[2][p], a2, wd2);
                FFMA2(acc[3][p], a2, wd3);
            }
        }

        // epilogue: per row assemble float4 (cols 4L..4L+3), act/resid, coalesced STG.128
#pragma unroll
        for (int p = 0; p < 4; p++) {
            float2 t0 = unpack2(acc[0][p]);
            float2 t1 = unpack2(acc[1][p]);
            float2 t2 = unpack2(acc[2][p]);
            float2 t3 = unpack2(acc[3][p]);
#pragma unroll
            for (int hh = 0; hh < 2; hh++) {
                int row = r0 + 2 * p + hh;
                if (row < nrows) {
                    float4 v;
                    v.x = hh ? t0.y : t0.x;
                    v.y = hh ? t1.y : t1.x;
                    v.z = hh ? t2.y : t2.x;
                    v.w = hh ? t3.y : t3.x;
                    if (act) { v.x = ssp(v.x); v.y = ssp(v.y); v.z = ssp(v.z); v.w = ssp(v.w); }
                    if (resid) {
                        const float4 rv = *(const float4*)(resid + (size_t)row * 128 + 4 * L);
                        v.x += rv.x; v.y += rv.y; v.z += rv.z; v.w += rv.w;
                    }
                    *(float4*)(out + (size_t)row * 128 + 4 * L) = v;
                }
            }
        }
        __syncwarp();   // protect st reuse
    }
}

// ---------------- readout GEMM (KC=64): 32 rows/block, simple (single launch) ----------------
__global__ void gemm64_kernel(const float* __restrict__ in,
                              const float* __restrict__ W,
                              const float* __restrict__ bias,
                              float* __restrict__ out,
                              int nrows) {
    extern __shared__ float sm[];
    float* ws  = sm;                 // 128*64
    float* bs  = ws + 128 * 64;      // 64
    float* ins = bs + 64;            // 32*128
    int c = threadIdx.x;

    for (int idx = c; idx < 128 * 64; idx += 64) ws[idx] = W[idx];
    bs[c] = bias[c];

    int r0 = blockIdx.x * 32;
    for (int idx = c; idx < 32 * 128; idx += 64) {
        int r = idx >> 7, k = idx & 127;
        ins[idx] = (r0 + r < nrows) ? in[(size_t)(r0 + r) * 128 + k] : 0.0f;
    }
    __syncthreads();

    float b = bs[c];
    float acc[32];
#pragma unroll
    for (int r = 0; r < 32; r++) acc[r] = b;

#pragma unroll 4
    for (int k = 0; k < 128; k++) {
        float wv = ws[k * 64 + c];
#pragma unroll
        for (int r = 0; r < 32; r++) acc[r] += ins[r * 128 + k] * wv;
    }

#pragma unroll
    for (int r = 0; r < 32; r++) {
        int row = r0 + r;
        if (row < nrows) out[(size_t)row * 64 + c] = ssp(acc[r]);
    }
}

// ---------------- fused edge pipeline (round-6 verified structure; EW raised 16->18) ----------------
__global__ __launch_bounds__(32 * EW, 1)
void edge_kernel(const int* __restrict__ ei,
                 const float* __restrict__ w1,
                 const float* __restrict__ b1,
                 const float* __restrict__ w2,
                 const float* __restrict__ b2, int E) {
    extern __shared__ float sm[];
    float* w1s = sm;                          // 50*128 = 6400
    float* w2s = w1s + NGAUSS * FILT;         // 128*128 = 16384
    float* b1s = w2s + FILT * FILT;           // 128
    float* b2s = b1s + FILT;                  // 128
    float* pw  = b2s + FILT;                  // EW * PWF

    int tid = threadIdx.x;
    for (int i = tid; i < NGAUSS * FILT; i += 32 * EW) w1s[i] = w1[i];
    for (int i = tid; i < FILT * FILT;  i += 32 * EW) w2s[i] = w2[i];
    if (tid < FILT) { b1s[tid] = b1[tid]; b2s[tid] = b2[tid]; }
    __syncthreads();

    const int wid = tid >> 5;
    const int L   = tid & 31;
    float* gw = pw + wid * PWF;               // [50][GROW]
    float* aw = gw + NGAUSS * GROW;           // [128][GROW]

    unsigned long long b1d[4], b2d[4];
#pragma unroll
    for (int i = 0; i < 4; i++) {
        b1d[i] = dupf(b1s[4 * L + i]);
        b2d[i] = dupf(b2s[4 * L + i]);
    }

    const long long stride = (long long)gridDim.x * EW * EPB;
    for (long long base = ((long long)blockIdx.x * EW + wid) * EPB; base < E;
         base += stride) {

        long long jl = base + L; if (jl > (long long)E - 1) jl = E - 1;
        int j = (int)jl;
        int sj = 0, tj = 0; float dj = 0.f, Cj = 0.f;
        if (L < EPB) {
            sj = ei[j]; tj = ei[E + j]; dj = g_d[j];
            Cj = (base + L < E) ? g_cut[j] : 0.f;
        }
        float de[EPB];
#pragma unroll
        for (int e = 0; e < EPB; e++) de[e] = __shfl_sync(0xffffffffu, dj, e);

        {
            float off = (float)L * SPACING;
#pragma unroll
            for (int p = 0; p < 4; p++) {
                float ua = de[2*p]   - off;
                float ub = de[2*p+1] - off;
                *(float2*)(gw + GROW * L + 2 * p) =
                    make_float2(__expf(GCOEFF * ua * ua), __expf(GCOEFF * ub * ub));
            }
            if (L < NGAUSS - 32) {
                int k2 = L + 32;
                float o2 = (float)k2 * SPACING;
#pragma unroll
                for (int p = 0; p < 4; p++) {
                    float ua = de[2*p]   - o2;
                    float ub = de[2*p+1] - o2;
                    *(float2*)(gw + GROW * k2 + 2 * p) =
                        make_float2(__expf(GCOEFF * ua * ua), __expf(GCOEFF * ub * ub));
                }
            }
        }
        __syncwarp();

        // ---- stage 1: [8,50] @ [50,128] + b1 ----
        unsigned long long u[4][4];
#pragma unroll
        for (int i = 0; i < 4; i++) {
            u[i][0] = b1d[i]; u[i][1] = b1d[i]; u[i][2] = b1d[i]; u[i][3] = b1d[i];
        }
#pragma unroll 2
        for (int k = 0; k < NGAUSS; k++) {
            const float4 wv = *(const float4*)(w1s + k * FILT + 4 * L);
            unsigned long long wd0 = dupf(wv.x), wd1 = dupf(wv.y),
                               wd2 = dupf(wv.z), wd3 = dupf(wv.w);
#pragma unroll
            for (int p = 0; p < 4; p++) {
                unsigned long long a2 =
                    *(const unsigned long long*)(gw + GROW * k + 2 * p);
                FFMA2(u[0][p], a2, wd0);
                FFMA2(u[1][p], a2, wd1);
                FFMA2(u[2][p], a2, wd2);
                FFMA2(u[3][p], a2, wd3);
            }
        }

#pragma unroll
        for (int i = 0; i < 4; i++) {
#pragma unroll
            for (int p = 0; p < 4; p++) {
                float2 t = unpack2(u[i][p]);
                *(float2*)(aw + GROW * (4 * L + i) + 2 * p) =
                    make_float2(ssp(t.x), ssp(t.y));
            }
        }
        __syncwarp();

        // ---- stage 2: [8,128] @ [128,128] + b2 ----
        unsigned long long y[4][4];
#pragma unroll
        for (int i = 0; i < 4; i++) {
            y[i][0] = b2d[i]; y[i][1] = b2d[i]; y[i][2] = b2d[i]; y[i][3] = b2d[i];
        }
#pragma unroll 2
        for (int k = 0; k < FILT; k++) {
            const float4 wv = *(const float4*)(w2s + k * FILT + 4 * L);
            unsigned long long wd0 = dupf(wv.x), wd1 = dupf(wv.y),
                               wd2 = dupf(wv.z), wd3 = dupf(wv.w);
#pragma unroll
            for (int p = 0; p < 4; p++) {
                unsigned long long a2 =
                    *(const unsigned long long*)(aw + GROW * k + 2 * p);
                FFMA2(y[0][p], a2, wd0);
                FFMA2(y[1][p], a2, wd1);
                FFMA2(y[2][p], a2, wd2);
                FFMA2(y[3][p], a2, wd3);
            }
        }

        // ---- message: m = xl[src] * (y * C), scatter-add to agg[dst] ----
#pragma unroll
        for (int e = 0; e < EPB; e++) {
            int   sE = __shfl_sync(0xffffffffu, sj, e);
            int   tE = __shfl_sync(0xffffffffu, tj, e);
            float CE = __shfl_sync(0xffffffffu, Cj, e);
            const float4 xv = *(const float4*)(g_xl + (size_t)sE * H + 4 * L);
            const int p = e >> 1;
            float y0, y1, y2, y3;
            if ((e & 1) == 0) {
                y0 = unpack2(y[0][p]).x; y1 = unpack2(y[1][p]).x;
                y2 = unpack2(y[2][p]).x; y3 = unpack2(y[3][p]).x;
            } else {
                y0 = unpack2(y[0][p]).y; y1 = unpack2(y[1][p]).y;
                y2 = unpack2(y[2][p]).y; y3 = unpack2(y[3][p]).y;
            }
            float m0 = y0 * CE * xv.x;
            float m1 = y1 * CE * xv.y;
            float m2 = y2 * CE * xv.z;
            float m3 = y3 * CE * xv.w;
            float* dp = g_agg + (size_t)tE * H + 4 * L;
            asm volatile("red.global.add.v4.f32 [%0], {%1, %2, %3, %4};"
                         :: "l"(dp), "f"(m0), "f"(m1), "f"(m2), "f"(m3)
                         : "memory");
        }
        __syncwarp();
    }
}

// ---------------- readout: e/q dots + segment sums ----------------
__global__ void readout2_kernel(const float* __restrict__ hh,  // [N,64]
                                const float* __restrict__ ew, const float* __restrict__ ebp,
                                const float* __restrict__ qw, const float* __restrict__ qbp,
                                const int* __restrict__ batch,
                                float* __restrict__ out, int N, int G) {
    int gw_id = (blockIdx.x * blockDim.x + threadIdx.x) >> 5;
    int lane  = threadIdx.x & 31;
    if (gw_id >= N) return;
    float h0 = hh[(size_t)gw_id * 64 + lane];
    float h1 = hh[(size_t)gw_id * 64 + 32 + lane];
    float e = h0 * ew[lane] + h1 * ew[lane + 32];
    float q = h0 * qw[lane] + h1 * qw[lane + 32];
#pragma unroll
    for (int o = 16; o > 0; o >>= 1) {
        e += __shfl_down_sync(0xffffffffu, e, o);
        q += __shfl_down_sync(0xffffffffu, q, o);
    }
    if (lane == 0) {
        e += ebp[0];
        q += qbp[0];
        out[gw_id]     = e;
        out[N + gw_id] = q;
        int b = batch[gw_id];
        atomicAdd(out + 2 * N + b,     e);
        atomicAdd(out + 2 * N + G + b, q);
    }
}

// ---------------- host launcher ----------------
extern "C" void kernel_launch(void* const* d_in, const int* in_sizes, int n_in,
                              void* d_out, int out_size) {
    const int*   atoms   = (const int*)  d_in[0];
    const float* pos     = (const float*)d_in[1];
    const int*   batch   = (const int*)  d_in[2];
    const int*   ei      = (const int*)  d_in[3];
    const float* emb     = (const float*)d_in[4];
    const float* mlp_w1  = (const float*)d_in[5];
    const float* mlp_b1  = (const float*)d_in[6];
    const float* mlp_w2  = (const float*)d_in[7];
    const float* mlp_b2  = (const float*)d_in[8];
    const float* conv_w1 = (const float*)d_in[9];
    const float* conv_w2 = (const float*)d_in[10];
    const float* conv_b2 = (const float*)d_in[11];
    const float* int_w   = (const float*)d_in[12];
    const float* int_b   = (const float*)d_in[13];
    const float* lin1_w  = (const float*)d_in[14];
    const float* lin1_b  = (const float*)d_in[15];
    const float* e_w     = (const float*)d_in[16];
    const float* e_b     = (const float*)d_in[17];
    const float* q_w     = (const float*)d_in[18];
    const float* q_b     = (const float*)d_in[19];
    float* out = (float*)d_out;

    const int N = in_sizes[0];
    const int E = in_sizes[3] / 2;
    const int G = (out_size - 2 * N) / 2;
    const int L = in_sizes[5] / (NGAUSS * FILT);

    void *hp_, *xlp_, *aggp_, *tmpp_;
    cudaGetSymbolAddress(&hp_,   g_h);
    cudaGetSymbolAddress(&xlp_,  g_xl);
    cudaGetSymbolAddress(&aggp_, g_agg);
    cudaGetSymbolAddress(&tmpp_, g_tmp);
    float* hp   = (float*)hp_;
    float* xlp  = (float*)xlp_;
    float* aggp = (float*)aggp_;
    float* tmpp = (float*)tmpp_;

    const size_t ngemm_smem  = (size_t)(128 * 128 + 128 + GW * 128 * GROW) * sizeof(float);
    const size_t gemm64_smem = (size_t)(128 * 64 + 64 + 32 * 128) * sizeof(float);
    const size_t edge_smem   = (size_t)(NGAUSS * FILT + FILT * FILT + 2 * FILT
                                        + EW * PWF) * sizeof(float);

    cudaFuncSetAttribute(ngemm_kernel,  cudaFuncAttributeMaxDynamicSharedMemorySize, (int)ngemm_smem);
    cudaFuncSetAttribute(gemm64_kernel, cudaFuncAttributeMaxDynamicSharedMemorySize, (int)gemm64_smem);
    cudaFuncSetAttribute(edge_kernel,   cudaFuncAttributeMaxDynamicSharedMemorySize, (int)edge_smem);

    prep_kernel<<<(E + 255) / 256, 256>>>(pos, ei, E);
    embed_kernel<<<(N * H + 255) / 256, 256>>>(atoms, emb, N);

    for (int l = 0; l < L; l++) {
        // xl = h @ conv_w1[l]  (also zeroes g_agg rows for this layer)
        ngemm_kernel<<<148, 32 * GW, ngemm_smem>>>(
            hp, conv_w1 + (size_t)l * H * FILT, nullptr, nullptr, xlp, N, 0, 1);
        // fused edge MLP + gather/scatter (persistent, 1 block/SM)
        edge_kernel<<<148, 32 * EW, edge_smem>>>(
            ei,
            mlp_w1 + (size_t)l * NGAUSS * FILT,
            mlp_b1 + (size_t)l * FILT,
            mlp_w2 + (size_t)l * FILT * FILT,
            mlp_b2 + (size_t)l * FILT, E);
        // tmp = ssp(agg @ conv_w2[l] + b2)
        ngemm_kernel<<<148, 32 * GW, ngemm_smem>>>(
            aggp, conv_w2 + (size_t)l * FILT * H, conv_b2 + (size_t)l * H,
            nullptr, tmpp, N, 1, 0);
        // h = h + tmp @ int_w[l] + int_b[l]
        ngemm_kernel<<<148, 32 * GW, ngemm_smem>>>(
            tmpp, int_w + (size_t)l * H * H, int_b + (size_t)l * H,
            hp, hp, N, 0, 0);
    }

    // hh = ssp(h @ lin1_w + lin1_b)  -> g_tmp as [N,64]
    gemm64_kernel<<<(N + 31) / 32, 64, gemm64_smem>>>(hp, lin1_w, lin1_b, tmpp, N);

    cudaMemsetAsync(out + 2 * N, 0, (size_t)2 * G * sizeof(float));
    readout2_kernel<<<(N * 32 + 255) / 256, 256>>>(
        tmpp, e_w, e_b, q_w, q_b, batch, out, N, G);
}

// round 15
// speedup vs baseline: 1.2344x; 1.0586x over previous
#include <cuda_runtime.h>
#include <math.h>
#include <stdint.h>

// ---------------- problem constants (fixed shapes) ----------------
#define H      128
#define FILT   128
#define NGAUSS 50
#define NMAX   50000
#define EMAX   800000
#define SPACING  (10.0f/49.0f)
#define GCOEFF   (-12.005f)            // -0.5/(10/49)^2
#define PI_OVER_CUT 0.3141592653589793f

#define EW   16      // warps per edge-kernel block (EW=18 measured REGRESSION: SMSP 5/5/4/4 imbalance)
#define EPB  8       // edges per warp-group
#define GROW 10      // padded row stride (floats) for g/a arrays
#define PWF  (NGAUSS*GROW + FILT*GROW)   // per-warp smem floats = 500+1280 = 1780

#define GW   16      // warps per node-GEMM block
#define NROW 8       // rows per warp in node GEMM

// ---------------- scratch (device globals; no allocation allowed) ----------------
__device__ __align__(128) float g_h  [NMAX * H];
__device__ __align__(128) float g_xl [NMAX * H];
__device__ __align__(128) float g_agg[NMAX * H];
__device__ __align__(128) float g_tmp[NMAX * H];
__device__ __align__(128) float g_d  [EMAX];
__device__ __align__(128) float g_cut[EMAX];

// shifted softplus: log(1+e^x) - log2 = log(0.5 + 0.5*e^x)
__device__ __forceinline__ float ssp(float x) {
    return __logf(0.5f + 0.5f * __expf(x));
}

#define FFMA2(acc, a, b) \
    asm("fma.rn.f32x2 %0, %1, %2, %0;" : "+l"(acc) : "l"(a), "l"(b))

__device__ __forceinline__ unsigned long long dupf(float v) {
    unsigned long long r; unsigned x = __float_as_uint(v);
    asm("mov.b64 %0, {%1,%1};" : "=l"(r) : "r"(x));
    return r;
}
__device__ __forceinline__ float2 unpack2(unsigned long long v) {
    float a, b;
    asm("mov.b64 {%0,%1}, %2;" : "=f"(a), "=f"(b) : "l"(v));
    return make_float2(a, b);
}

// ---------------- edge geometry precompute ----------------
__global__ void prep_kernel(const float* __restrict__ pos,
                            const int* __restrict__ ei, int E) {
    int e = blockIdx.x * blockDim.x + threadIdx.x;
    if (e >= E) return;
    int s = ei[e];
    int t = ei[E + e];
    float dx = pos[3*s+0] - pos[3*t+0];
    float dy = pos[3*s+1] - pos[3*t+1];
    float dz = pos[3*s+2] - pos[3*t+2];
    float d = sqrtf(dx*dx + dy*dy + dz*dz);
    g_d[e]   = d;
    g_cut[e] = 0.5f * (cosf(d * PI_OVER_CUT) + 1.0f);
}

// ---------------- embedding ----------------
__global__ void embed_kernel(const int* __restrict__ atoms,
                             const float* __restrict__ emb, int N) {
    int i = blockIdx.x * blockDim.x + threadIdx.x;
    if (i >= N * H) return;
    g_h[i] = emb[atoms[i >> 7] * H + (i & (H - 1))];
}

// ---------------- node GEMM (KC=128): out = [ssp](in @ W + bias) [+ resid] ----------------
// VERIFIED (round 14): ~45us/launch vs ~115us old layout.
// Warp owns 8 rows, lane owns 4 cols. Per k:
// 1 LDS.128 (weights) + 4 dup movs + 4 broadcast LDS.64 (row pairs) + 16 FFMA2.
// Persistent grid: weights loaded into smem ONCE per SM.
// If zero_agg != 0, also zeroes the processed rows of g_agg.
__global__ __launch_bounds__(32 * GW, 1)
void ngemm_kernel(const float* __restrict__ in,
                  const float* __restrict__ W,
                  const float* __restrict__ bias,
                  const float* __restrict__ resid,
                  float* __restrict__ out,
                  int nrows, int act, int zero_agg) {
    extern __shared__ float sm[];
    float* ws = sm;                       // 128*128
    float* bs = ws + 128 * 128;           // 128
    float* pw = bs + 128;                 // GW * 128 * GROW (per-warp k-major staging)

    int tid = threadIdx.x;
    for (int i = tid; i < 128 * 128; i += 32 * GW) ws[i] = W[i];
    if (tid < 128) bs[tid] = bias ? bias[tid] : 0.0f;
    __syncthreads();

    const int wid = tid >> 5;
    const int L   = tid & 31;
    float* st = pw + wid * (128 * GROW);  // [128 k][GROW] (8 rows + 2 pad)

    unsigned long long bd[4];
#pragma unroll
    for (int i = 0; i < 4; i++) bd[i] = dupf(bs[4 * L + i]);

    const int ngroups = (nrows + NROW - 1) / NROW;
    const int gstride = gridDim.x * GW;
    for (int g = blockIdx.x * GW + wid; g < ngroups; g += gstride) {
        const int r0 = g * NROW;

        // stage 8 rows k-major: st[k][r] = in[r0+r][k]; coalesced LDG
        for (int i = L; i < NROW * 128; i += 32) {
            int r = i >> 7, k = i & 127;
            float v = (r0 + r < nrows) ? in[(size_t)(r0 + r) * 128 + k] : 0.0f;
            st[k * GROW + r] = v;
            if (zero_agg && r0 + r < nrows) g_agg[(size_t)(r0 + r) * 128 + k] = 0.0f;
        }
        __syncwarp();

        unsigned long long acc[4][4];
#pragma unroll
        for (int i = 0; i < 4; i++) {
            acc[i][0] = bd[i]; acc[i][1] = bd[i]; acc[i][2] = bd[i]; acc[i][3] = bd[i];
        }

#pragma unroll 2
        for (int k = 0; k < 128; k++) {
            const float4 wv = *(const float4*)(ws + k * 128 + 4 * L);
            unsigned long long wd0 = dupf(wv.x), wd1 = dupf(wv.y),
                               wd2 = dupf(wv.z), wd3 = dupf(wv.w);
#pragma unroll
            for (int p = 0; p < 4; p++) {
                unsigned long long a2 =
                    *(const unsigned long long*)(st + k * GROW + 2 * p);
                FFMA2(acc[0][p], a2, wd0);
                FFMA2(acc[1][p], a2, wd1);
                FFMA2(acc[2][p], a2, wd2);
                FFMA2(acc[3][p], a2, wd3);
            }
        }

        // epilogue: per row assemble float4 (cols 4L..4L+3), act/resid, coalesced STG.128
#pragma unroll
        for (int p = 0; p < 4; p++) {
            float2 t0 = unpack2(acc[0][p]);
            float2 t1 = unpack2(acc[1][p]);
            float2 t2 = unpack2(acc[2][p]);
            float2 t3 = unpack2(acc[3][p]);
#pragma unroll
            for (int hh = 0; hh < 2; hh++) {
                int row = r0 + 2 * p + hh;
                if (row < nrows) {
                    float4 v;
                    v.x = hh ? t0.y : t0.x;
                    v.y = hh ? t1.y : t1.x;
                    v.z = hh ? t2.y : t2.x;
                    v.w = hh ? t3.y : t3.x;
                    if (act) { v.x = ssp(v.x); v.y = ssp(v.y); v.z = ssp(v.z); v.w = ssp(v.w); }
                    if (resid) {
                        const float4 rv = *(const float4*)(resid + (size_t)row * 128 + 4 * L);
                        v.x += rv.x; v.y += rv.y; v.z += rv.z; v.w += rv.w;
                    }
                    *(float4*)(out + (size_t)row * 128 + 4 * L) = v;
                }
            }
        }
        __syncwarp();   // protect st reuse
    }
}

// ---------------- readout GEMM (KC=64): 32 rows/block, simple (single launch) ----------------
__global__ void gemm64_kernel(const float* __restrict__ in,
                              const float* __restrict__ W,
                              const float* __restrict__ bias,
                              float* __restrict__ out,
                              int nrows) {
    extern __shared__ float sm[];
    float* ws  = sm;                 // 128*64
    float* bs  = ws + 128 * 64;      // 64
    float* ins = bs + 64;            // 32*128
    int c = threadIdx.x;

    for (int idx = c; idx < 128 * 64; idx += 64) ws[idx] = W[idx];
    bs[c] = bias[c];

    int r0 = blockIdx.x * 32;
    for (int idx = c; idx < 32 * 128; idx += 64) {
        int r = idx >> 7, k = idx & 127;
        ins[idx] = (r0 + r < nrows) ? in[(size_t)(r0 + r) * 128 + k] : 0.0f;
    }
    __syncthreads();

    float b = bs[c];
    float acc[32];
#pragma unroll
    for (int r = 0; r < 32; r++) acc[r] = b;

#pragma unroll 4
    for (int k = 0; k < 128; k++) {
        float wv = ws[k * 64 + c];
#pragma unroll
        for (int r = 0; r < 32; r++) acc[r] += ins[r * 128 + k] * wv;
    }

#pragma unroll
    for (int r = 0; r < 32; r++) {
        int row = r0 + r;
        if (row < nrows) out[(size_t)row * 64 + c] = ssp(acc[r]);
    }
}

// ---------------- fused edge pipeline (round-6 verified config: 715us/layer @ EW=16) ----------------
__global__ __launch_bounds__(32 * EW, 1)
void edge_kernel(const int* __restrict__ ei,
                 const float* __restrict__ w1,
                 const float* __restrict__ b1,
                 const float* __restrict__ w2,
                 const float* __restrict__ b2, int E) {
    extern __shared__ float sm[];
    float* w1s = sm;                          // 50*128 = 6400
    float* w2s = w1s + NGAUSS * FILT;         // 128*128 = 16384
    float* b1s = w2s + FILT * FILT;           // 128
    float* b2s = b1s + FILT;                  // 128
    float* pw  = b2s + FILT;                  // EW * PWF

    int tid = threadIdx.x;
    for (int i = tid; i < NGAUSS * FILT; i += 32 * EW) w1s[i] = w1[i];
    for (int i = tid; i < FILT * FILT;  i += 32 * EW) w2s[i] = w2[i];
    if (tid < FILT) { b1s[tid] = b1[tid]; b2s[tid] = b2[tid]; }
    __syncthreads();

    const int wid = tid >> 5;
    const int L   = tid & 31;
    float* gw = pw + wid * PWF;               // [50][GROW]
    float* aw = gw + NGAUSS * GROW;           // [128][GROW]

    unsigned long long b1d[4], b2d[4];
#pragma unroll
    for (int i = 0; i < 4; i++) {
        b1d[i] = dupf(b1s[4 * L + i]);
        b2d[i] = dupf(b2s[4 * L + i]);
    }

    const long long stride = (long long)gridDim.x * EW * EPB;
    for (long long base = ((long long)blockIdx.x * EW + wid) * EPB; base < E;
         base += stride) {

        long long jl = base + L; if (jl > (long long)E - 1) jl = E - 1;
        int j = (int)jl;
        int sj = 0, tj = 0; float dj = 0.f, Cj = 0.f;
        if (L < EPB) {
            sj = ei[j]; tj = ei[E + j]; dj = g_d[j];
            Cj = (base + L < E) ? g_cut[j] : 0.f;
        }
        float de[EPB];
#pragma unroll
        for (int e = 0; e < EPB; e++) de[e] = __shfl_sync(0xffffffffu, dj, e);

        {
            float off = (float)L * SPACING;
#pragma unroll
            for (int p = 0; p < 4; p++) {
                float ua = de[2*p]   - off;
                float ub = de[2*p+1] - off;
                *(float2*)(gw + GROW * L + 2 * p) =
                    make_float2(__expf(GCOEFF * ua * ua), __expf(GCOEFF * ub * ub));
            }
            if (L < NGAUSS - 32) {
                int k2 = L + 32;
                float o2 = (float)k2 * SPACING;
#pragma unroll
                for (int p = 0; p < 4; p++) {
                    float ua = de[2*p]   - o2;
                    float ub = de[2*p+1] - o2;
                    *(float2*)(gw + GROW * k2 + 2 * p) =
                        make_float2(__expf(GCOEFF * ua * ua), __expf(GCOEFF * ub * ub));
                }
            }
        }
        __syncwarp();

        // ---- stage 1: [8,50] @ [50,128] + b1 ----
        unsigned long long u[4][4];
#pragma unroll
        for (int i = 0; i < 4; i++) {
            u[i][0] = b1d[i]; u[i][1] = b1d[i]; u[i][2] = b1d[i]; u[i][3] = b1d[i];
        }
#pragma unroll 2
        for (int k = 0; k < NGAUSS; k++) {
            const float4 wv = *(const float4*)(w1s + k * FILT + 4 * L);
            unsigned long long wd0 = dupf(wv.x), wd1 = dupf(wv.y),
                               wd2 = dupf(wv.z), wd3 = dupf(wv.w);
#pragma unroll
            for (int p = 0; p < 4; p++) {
                unsigned long long a2 =
                    *(const unsigned long long*)(gw + GROW * k + 2 * p);
                FFMA2(u[0][p], a2, wd0);
                FFMA2(u[1][p], a2, wd1);
                FFMA2(u[2][p], a2, wd2);
                FFMA2(u[3][p], a2, wd3);
            }
        }

#pragma unroll
        for (int i = 0; i < 4; i++) {
#pragma unroll
            for (int p = 0; p < 4; p++) {
                float2 t = unpack2(u[i][p]);
                *(float2*)(aw + GROW * (4 * L + i) + 2 * p) =
                    make_float2(ssp(t.x), ssp(t.y));
            }
        }
        __syncwarp();

        // ---- stage 2: [8,128] @ [128,128] + b2 ----
        unsigned long long y[4][4];
#pragma unroll
        for (int i = 0; i < 4; i++) {
            y[i][0] = b2d[i]; y[i][1] = b2d[i]; y[i][2] = b2d[i]; y[i][3] = b2d[i];
        }
#pragma unroll 2
        for (int k = 0; k < FILT; k++) {
            const float4 wv = *(const float4*)(w2s + k * FILT + 4 * L);
            unsigned long long wd0 = dupf(wv.x), wd1 = dupf(wv.y),
                               wd2 = dupf(wv.z), wd3 = dupf(wv.w);
#pragma unroll
            for (int p = 0; p < 4; p++) {
                unsigned long long a2 =
                    *(const unsigned long long*)(aw + GROW * k + 2 * p);
                FFMA2(y[0][p], a2, wd0);
                FFMA2(y[1][p], a2, wd1);
                FFMA2(y[2][p], a2, wd2);
                FFMA2(y[3][p], a2, wd3);
            }
        }

        // ---- message: m = xl[src] * (y * C), scatter-add to agg[dst] ----
#pragma unroll
        for (int e = 0; e < EPB; e++) {
            int   sE = __shfl_sync(0xffffffffu, sj, e);
            int   tE = __shfl_sync(0xffffffffu, tj, e);
            float CE = __shfl_sync(0xffffffffu, Cj, e);
            const float4 xv = *(const float4*)(g_xl + (size_t)sE * H + 4 * L);
            const int p = e >> 1;
            float y0, y1, y2, y3;
            if ((e & 1) == 0) {
                y0 = unpack2(y[0][p]).x; y1 = unpack2(y[1][p]).x;
                y2 = unpack2(y[2][p]).x; y3 = unpack2(y[3][p]).x;
            } else {
                y0 = unpack2(y[0][p]).y; y1 = unpack2(y[1][p]).y;
                y2 = unpack2(y[2][p]).y; y3 = unpack2(y[3][p]).y;
            }
            float m0 = y0 * CE * xv.x;
            float m1 = y1 * CE * xv.y;
            float m2 = y2 * CE * xv.z;
            float m3 = y3 * CE * xv.w;
            float* dp = g_agg + (size_t)tE * H + 4 * L;
            asm volatile("red.global.add.v4.f32 [%0], {%1, %2, %3, %4};"
                         :: "l"(dp), "f"(m0), "f"(m1), "f"(m2), "f"(m3)
                         : "memory");
        }
        __syncwarp();
    }
}

// ---------------- readout: e/q dots + segment sums ----------------
__global__ void readout2_kernel(const float* __restrict__ hh,  // [N,64]
                                const float* __restrict__ ew, const float* __restrict__ ebp,
                                const float* __restrict__ qw, const float* __restrict__ qbp,
                                const int* __restrict__ batch,
                                float* __restrict__ out, int N, int G) {
    int gw_id = (blockIdx.x * blockDim.x + threadIdx.x) >> 5;
    int lane  = threadIdx.x & 31;
    if (gw_id >= N) return;
    float h0 = hh[(size_t)gw_id * 64 + lane];
    float h1 = hh[(size_t)gw_id * 64 + 32 + lane];
    float e = h0 * ew[lane] + h1 * ew[lane + 32];
    float q = h0 * qw[lane] + h1 * qw[lane + 32];
#pragma unroll
    for (int o = 16; o > 0; o >>= 1) {
        e += __shfl_down_sync(0xffffffffu, e, o);
        q += __shfl_down_sync(0xffffffffu, q, o);
    }
    if (lane == 0) {
        e += ebp[0];
        q += qbp[0];
        out[gw_id]     = e;
        out[N + gw_id] = q;
        int b = batch[gw_id];
        atomicAdd(out + 2 * N + b,     e);
        atomicAdd(out + 2 * N + G + b, q);
    }
}

// ---------------- host launcher ----------------
extern "C" void kernel_launch(void* const* d_in, const int* in_sizes, int n_in,
                              void* d_out, int out_size) {
    const int*   atoms   = (const int*)  d_in[0];
    const float* pos     = (const float*)d_in[1];
    const int*   batch   = (const int*)  d_in[2];
    const int*   ei      = (const int*)  d_in[3];
    const float* emb     = (const float*)d_in[4];
    const float* mlp_w1  = (const float*)d_in[5];
    const float* mlp_b1  = (const float*)d_in[6];
    const float* mlp_w2  = (const float*)d_in[7];
    const float* mlp_b2  = (const float*)d_in[8];
    const float* conv_w1 = (const float*)d_in[9];
    const float* conv_w2 = (const float*)d_in[10];
    const float* conv_b2 = (const float*)d_in[11];
    const float* int_w   = (const float*)d_in[12];
    const float* int_b   = (const float*)d_in[13];
    const float* lin1_w  = (const float*)d_in[14];
    const float* lin1_b  = (const float*)d_in[15];
    const float* e_w     = (const float*)d_in[16];
    const float* e_b     = (const float*)d_in[17];
    const float* q_w     = (const float*)d_in[18];
    const float* q_b     = (const float*)d_in[19];
    float* out = (float*)d_out;

    const int N = in_sizes[0];
    const int E = in_sizes[3] / 2;
    const int G = (out_size - 2 * N) / 2;
    const int L = in_sizes[5] / (NGAUSS * FILT);

    void *hp_, *xlp_, *aggp_, *tmpp_;
    cudaGetSymbolAddress(&hp_,   g_h);
    cudaGetSymbolAddress(&xlp_,  g_xl);
    cudaGetSymbolAddress(&aggp_, g_agg);
    cudaGetSymbolAddress(&tmpp_, g_tmp);
    float* hp   = (float*)hp_;
    float* xlp  = (float*)xlp_;
    float* aggp = (float*)aggp_;
    float* tmpp = (float*)tmpp_;

    const size_t ngemm_smem  = (size_t)(128 * 128 + 128 + GW * 128 * GROW) * sizeof(float);
    const size_t gemm64_smem = (size_t)(128 * 64 + 64 + 32 * 128) * sizeof(float);
    const size_t edge_smem   = (size_t)(NGAUSS * FILT + FILT * FILT + 2 * FILT
                                        + EW * PWF) * sizeof(float);

    cudaFuncSetAttribute(ngemm_kernel,  cudaFuncAttributeMaxDynamicSharedMemorySize, (int)ngemm_smem);
    cudaFuncSetAttribute(gemm64_kernel, cudaFuncAttributeMaxDynamicSharedMemorySize, (int)gemm64_smem);
    cudaFuncSetAttribute(edge_kernel,   cudaFuncAttributeMaxDynamicSharedMemorySize, (int)edge_smem);

    prep_kernel<<<(E + 255) / 256, 256>>>(pos, ei, E);
    embed_kernel<<<(N * H + 255) / 256, 256>>>(atoms, emb, N);

    for (int l = 0; l < L; l++) {
        // xl = h @ conv_w1[l]  (also zeroes g_agg rows for this layer)
        ngemm_kernel<<<148, 32 * GW, ngemm_smem>>>(
            hp, conv_w1 + (size_t)l * H * FILT, nullptr, nullptr, xlp, N, 0, 1);
        // fused edge MLP + gather/scatter (persistent, 1 block/SM)
        edge_kernel<<<148, 32 * EW, edge_smem>>>(
            ei,
            mlp_w1 + (size_t)l * NGAUSS * FILT,
            mlp_b1 + (size_t)l * FILT,
            mlp_w2 + (size_t)l * FILT * FILT,
            mlp_b2 + (size_t)l * FILT, E);
        // tmp = ssp(agg @ conv_w2[l] + b2)
        ngemm_kernel<<<148, 32 * GW, ngemm_smem>>>(
            aggp, conv_w2 + (size_t)l * FILT * H, conv_b2 + (size_t)l * H,
            nullptr, tmpp, N, 1, 0);
        // h = h + tmp @ int_w[l] + int_b[l]
        ngemm_kernel<<<148, 32 * GW, ngemm_smem>>>(
            tmpp, int_w + (size_t)l * H * H, int_b + (size_t)l * H,
            hp, hp, N, 0, 0);
    }

    // hh = ssp(h @ lin1_w + lin1_b)  -> g_tmp as [N,64]
    gemm64_kernel<<<(N + 31) / 32, 64, gemm64_smem>>>(hp, lin1_w, lin1_b, tmpp, N);

    cudaMemsetAsync(out + 2 * N, 0, (size_t)2 * G * sizeof(float));
    readout2_kernel<<<(N * 32 + 255) / 256, 256>>>(
        tmpp, e_w, e_b, q_w, q_b, batch, out, N, G);
}